// round 9
// baseline (speedup 1.0000x reference)
#include <cuda_runtime.h>
#include <cstdint>

#define BB   4
#define NN   2048
#define DD   1024
#define EE   8
#define BTL  128
#define TOPK 2
#define BE   (BB*EE)
#define BND  (BB*NN*DD)

// ---------------- static device scratch ----------------
__device__ int    g_list[BE*NN];
__device__ float  g_wlist[BE*NN];
__device__ int    g_cnt[BE];
__device__ int2   g_topi[BB*NN];
__device__ float2 g_w[BB*NN];
__device__ float  g_probs[BB*NN*EE];
__device__ float  g_psum[EE];
__device__ float  g_fsum[EE];
__device__ float  g_act;
__device__ float  g_h[(size_t)BE*NN*BTL];
__device__ float  g_q[(size_t)BE*NN*BTL];
__device__ float  g_k[(size_t)BE*NN*BTL];
__device__ float  g_v[(size_t)BE*NN*BTL];
__device__ float  g_o[(size_t)BE*NN*BTL];

// ---------------- tf32 helpers ----------------
__device__ __forceinline__ void split_tf32(float x, uint32_t& hi, uint32_t& lo) {
    asm("cvt.rna.tf32.f32 %0, %1;" : "=r"(hi) : "f"(x));
    float r = x - __uint_as_float(hi);
    asm("cvt.rna.tf32.f32 %0, %1;" : "=r"(lo) : "f"(r));
}

__device__ __forceinline__ void mma_tf32(float* d, const uint32_t* a, const uint32_t* b) {
    asm("mma.sync.aligned.m16n8k8.row.col.f32.tf32.tf32.f32 "
        "{%0,%1,%2,%3}, {%4,%5,%6,%7}, {%8,%9}, {%0,%1,%2,%3};"
        : "+f"(d[0]), "+f"(d[1]), "+f"(d[2]), "+f"(d[3])
        : "r"(a[0]), "r"(a[1]), "r"(a[2]), "r"(a[3]), "r"(b[0]), "r"(b[1]));
}

__device__ __forceinline__ void frag4(const float* p, uint32_t* r) {
    float4 v = *(const float4*)p;
    r[0]=__float_as_uint(v.x); r[1]=__float_as_uint(v.y);
    r[2]=__float_as_uint(v.z); r[3]=__float_as_uint(v.w);
}
__device__ __forceinline__ void frag2(const float* p, uint32_t* r) {
    float2 v = *(const float2*)p;
    r[0]=__float_as_uint(v.x); r[1]=__float_as_uint(v.y);
}

// Permuted smem layouts (verified by R6 pass):
// A element (m,k): addr = ((m>>4)*4 + (k>>3))*128 + ((m&7)<<4) + (k&3)*4
//                  + (((m>>3)&1) | (((k>>2)&1)<<1))
// B element (k,n): addr = ((n>>3)*4 + (k>>3))*64 + ((n&7)<<3) + ((k&3)<<1) + ((k>>2)&1)
// hi and lo stored in parallel arrays at identical offsets.

// dynamic smem: AH[2048] AL[2048] BH[4096] BL[4096] = 48KB
#define GEMM_SMEM (12288*4)

#define MMA_CHUNK(AH, AL, BH, BL, d, warp_m, warp_n, lane)                           \
    _Pragma("unroll")                                                                \
    for (int ks = 0; ks < 4; ks++) {                                                 \
        uint32_t ah[2][4], al[2][4], bh[4][2], bl[4][2];                             \
        _Pragma("unroll")                                                            \
        for (int mt = 0; mt < 2; mt++) {                                             \
            int off = ((((warp_m)*2+mt)*4+ks)<<7) + ((lane)<<2);                     \
            frag4((AH)+off, ah[mt]);                                                 \
            frag4((AL)+off, al[mt]);                                                 \
        }                                                                            \
        _Pragma("unroll")                                                            \
        for (int nt = 0; nt < 4; nt++) {                                             \
            int off = ((((warp_n)*4+nt)*4+ks)<<6) + ((lane)<<1);                     \
            frag2((BH)+off, bh[nt]);                                                 \
            frag2((BL)+off, bl[nt]);                                                 \
        }                                                                            \
        _Pragma("unroll")                                                            \
        for (int mt = 0; mt < 2; mt++)                                               \
            _Pragma("unroll")                                                        \
            for (int nt = 0; nt < 4; nt++) {                                         \
                mma_tf32(d[mt][nt], ah[mt], bh[nt]);                                 \
                mma_tf32(d[mt][nt], ah[mt], bl[nt]);                                 \
                mma_tf32(d[mt][nt], al[mt], bh[nt]);                                 \
            }                                                                        \
    }

// store one float4 of A (row r, k-quad kq) pre-split
#define STORE_A(AH, AL, r, kq, v)                                                    \
    {                                                                                \
        int base = ((((r) >> 4) * 4 + ((kq) >> 1)) << 7) + (((r) & 7) << 4)          \
                 + ((((r) >> 3) & 1) | (((kq) & 1) << 1));                           \
        uint32_t h_, l_;                                                             \
        split_tf32((v).x, h_, l_); (AH)[base]    = __uint_as_float(h_); (AL)[base]    = __uint_as_float(l_); \
        split_tf32((v).y, h_, l_); (AH)[base+4]  = __uint_as_float(h_); (AL)[base+4]  = __uint_as_float(l_); \
        split_tf32((v).z, h_, l_); (AH)[base+8]  = __uint_as_float(h_); (AL)[base+8]  = __uint_as_float(l_); \
        split_tf32((v).w, h_, l_); (AH)[base+12] = __uint_as_float(h_); (AL)[base+12] = __uint_as_float(l_); \
    }

// store one float4 of B (k-row kr, cols n..n+3) pre-split
#define STORE_B(BH, BL, kr, n, v)                                                    \
    {                                                                                \
        int base = ((((n) >> 3) * 4 + ((kr) >> 3)) << 6) + (((n) & 7) << 3)          \
                 + (((kr) & 3) << 1) + (((kr) >> 2) & 1);                            \
        uint32_t h_, l_;                                                             \
        split_tf32((v).x, h_, l_); (BH)[base]    = __uint_as_float(h_); (BL)[base]    = __uint_as_float(l_); \
        split_tf32((v).y, h_, l_); (BH)[base+8]  = __uint_as_float(h_); (BL)[base+8]  = __uint_as_float(l_); \
        split_tf32((v).z, h_, l_); (BH)[base+16] = __uint_as_float(h_); (BL)[base+16] = __uint_as_float(l_); \
        split_tf32((v).w, h_, l_); (BH)[base+24] = __uint_as_float(h_); (BL)[base+24] = __uint_as_float(l_); \
    }

// ---------------- router: 1 warp per token ----------------
__global__ void __launch_bounds__(256) router_kernel(const float* __restrict__ x,
                                                     const float* __restrict__ Wg) {
    int token = (blockIdx.x * blockDim.x + threadIdx.x) >> 5;
    int lane  = threadIdx.x & 31;
    float acc[EE];
#pragma unroll
    for (int e = 0; e < EE; e++) acc[e] = 0.f;
    const float* xr = x + (size_t)token * DD;
    for (int d = lane; d < DD; d += 32) {
        float xv = xr[d];
        const float4 w0 = *(const float4*)(Wg + d*EE);
        const float4 w1 = *(const float4*)(Wg + d*EE + 4);
        acc[0] += xv*w0.x; acc[1] += xv*w0.y; acc[2] += xv*w0.z; acc[3] += xv*w0.w;
        acc[4] += xv*w1.x; acc[5] += xv*w1.y; acc[6] += xv*w1.z; acc[7] += xv*w1.w;
    }
#pragma unroll
    for (int off = 16; off; off >>= 1)
#pragma unroll
        for (int e = 0; e < EE; e++)
            acc[e] += __shfl_xor_sync(0xffffffffu, acc[e], off);
    if (lane == 0) {
        float m = acc[0];
#pragma unroll
        for (int e = 1; e < EE; e++) m = fmaxf(m, acc[e]);
        float p[EE], s = 0.f;
#pragma unroll
        for (int e = 0; e < EE; e++) { p[e] = expf(acc[e] - m); s += p[e]; }
        float inv = 1.f / s;
#pragma unroll
        for (int e = 0; e < EE; e++) { p[e] *= inv; g_probs[token*EE + e] = p[e]; }
        int i1 = 0; float v1 = p[0];
#pragma unroll
        for (int e = 1; e < EE; e++) if (p[e] > v1) { v1 = p[e]; i1 = e; }
        int i2 = -1; float v2 = -1.f;
#pragma unroll
        for (int e = 0; e < EE; e++) if (e != i1 && p[e] > v2) { v2 = p[e]; i2 = e; }
        float ws = v1 + v2;
        g_topi[token] = make_int2(i1, i2);
        g_w[token]    = make_float2(v1/ws, v2/ws);
    }
}

// ---------------- deterministic router stats ----------------
__global__ void router_reduce(const int* __restrict__ act) {
    int w = threadIdx.x >> 5, lane = threadIdx.x & 31;
    if (w < EE) {
        float ps = 0.f, fs = 0.f;
        for (int t = lane; t < BB*NN; t += 32) {
            float a = (act[t] != 0) ? 1.f : 0.f;
            ps += g_probs[t*EE + w] * a;
            int2 ti = g_topi[t];
            if (ti.x == w || ti.y == w) fs += a;
        }
#pragma unroll
        for (int off = 16; off; off >>= 1) {
            ps += __shfl_xor_sync(0xffffffffu, ps, off);
            fs += __shfl_xor_sync(0xffffffffu, fs, off);
        }
        if (lane == 0) { g_psum[w] = ps; g_fsum[w] = fs; }
    } else if (w == EE) {
        float s = 0.f;
        for (int t = lane; t < BB*NN; t += 32) s += (act[t] != 0) ? 1.f : 0.f;
#pragma unroll
        for (int off = 16; off; off >>= 1) s += __shfl_xor_sync(0xffffffffu, s, off);
        if (lane == 0) g_act = s;
    }
}

// ---------------- compact token lists per (b,e) ----------------
__global__ void build_lists(const int* __restrict__ act) {
    int be = blockIdx.x; int b = be >> 3, e = be & 7;
    __shared__ int s_scan[256];
    __shared__ int s_base;
    int tid = threadIdx.x;
    if (tid == 0) s_base = 0;
    __syncthreads();
    for (int c0 = 0; c0 < NN; c0 += 256) {
        int n = c0 + tid;
        int2 ti = g_topi[b*NN + n];
        int hit1 = (ti.x == e), hit2 = (ti.y == e);
        int f = ((hit1 || hit2) && (act[b*NN + n] != 0)) ? 1 : 0;
        s_scan[tid] = f;
        __syncthreads();
        int val = f;
        for (int off = 1; off < 256; off <<= 1) {
            int add = (tid >= off) ? s_scan[tid - off] : 0;
            __syncthreads();
            val += add;
            s_scan[tid] = val;
            __syncthreads();
        }
        if (f) {
            int pos = s_base + val - 1;
            g_list[be*NN + pos]  = n;
            float2 w = g_w[b*NN + n];
            g_wlist[be*NN + pos] = hit1 ? w.x : w.y;
        }
        __syncthreads();
        if (tid == 0) s_base += s_scan[255];
        __syncthreads();
    }
    if (tid == 0) g_cnt[be] = s_base;
}

// ---------------- down: h = gather(x) @ Wd[e], 3xTF32 mma, pre-split ------
__global__ void __launch_bounds__(256) down_gemm(const float* __restrict__ x,
                                                 const float* __restrict__ Wd) {
    int be = blockIdx.y; int b = be >> 3, e = be & 7;
    int T  = g_cnt[be];
    int m0 = blockIdx.x << 6;
    if (m0 >= T) return;
    extern __shared__ float sm[];
    float* AH = sm;
    float* AL = sm + 2048;
    float* BH = sm + 4096;
    float* BL = sm + 8192;
    __shared__ int rtok[64];
    int tid = threadIdx.x, lane = tid & 31, wid = tid >> 5;
    int warp_m = wid >> 2, warp_n = wid & 3;
    if (tid < 64) {
        int r = m0 + tid;
        rtok[tid] = (r < T) ? g_list[be*NN + r] : g_list[be*NN];
    }
    float d[2][4][4];
#pragma unroll
    for (int mt = 0; mt < 2; mt++)
#pragma unroll
        for (int nt = 0; nt < 4; nt++)
#pragma unroll
            for (int i = 0; i < 4; i++) d[mt][nt][i] = 0.f;
    const float* Wde = Wd + (size_t)e * DD * BTL;
    for (int ko = 0; ko < DD; ko += 32) {
        __syncthreads();
#pragma unroll
        for (int t = 0; t < 2; t++) {
            int idx = tid + (t << 8);
            int r = idx >> 3, kq = idx & 7;
            float4 v = *(const float4*)(x + (size_t)(b*NN + rtok[r])*DD + ko + (kq << 2));
            STORE_A(AH, AL, r, kq, v)
        }
#pragma unroll
        for (int t = 0; t < 4; t++) {
            int idx = tid + (t << 8);
            int kr = idx >> 5, n = (idx & 31) << 2;
            float4 v = *(const float4*)(Wde + (size_t)(ko + kr)*BTL + n);
            STORE_B(BH, BL, kr, n, v)
        }
        __syncthreads();
        MMA_CHUNK(AH, AL, BH, BL, d, warp_m, warp_n, lane)
    }
#pragma unroll
    for (int mt = 0; mt < 2; mt++)
#pragma unroll
        for (int nt = 0; nt < 4; nt++) {
            int row = warp_m*32 + mt*16 + (lane >> 2);
            int col = warp_n*32 + nt*8 + ((lane & 3) << 1);
            int r0 = m0 + row, r1 = r0 + 8;
            if (r0 < T)
                *(float2*)&g_h[((size_t)be*NN + r0)*BTL + col] = make_float2(d[mt][nt][0], d[mt][nt][1]);
            if (r1 < T)
                *(float2*)&g_h[((size_t)be*NN + r1)*BTL + col] = make_float2(d[mt][nt][2], d[mt][nt][3]);
        }
}

// ---------------- qkv: q/k/v = h @ W_{q,k,v}[e] ----------------
__global__ void __launch_bounds__(256) qkv_gemm(const float* __restrict__ Wq,
                                                const float* __restrict__ Wk,
                                                const float* __restrict__ Wv) {
    int be = blockIdx.y; int e = be & 7;
    int T  = g_cnt[be];
    int m0 = blockIdx.x << 6;
    if (m0 >= T) return;
    int z = blockIdx.z;
    const float* Bmat = ((z == 0) ? Wq : (z == 1) ? Wk : Wv) + (size_t)e*BTL*BTL;
    float* Cout = (z == 0) ? g_q : (z == 1) ? g_k : g_v;
    const float* Abase = g_h + (size_t)be*NN*BTL;
    extern __shared__ float sm[];
    float* AH = sm;
    float* AL = sm + 2048;
    float* BH = sm + 4096;
    float* BL = sm + 8192;
    int tid = threadIdx.x, lane = tid & 31, wid = tid >> 5;
    int warp_m = wid >> 2, warp_n = wid & 3;
    float d[2][4][4];
#pragma unroll
    for (int mt = 0; mt < 2; mt++)
#pragma unroll
        for (int nt = 0; nt < 4; nt++)
#pragma unroll
            for (int i = 0; i < 4; i++) d[mt][nt][i] = 0.f;
    for (int ko = 0; ko < BTL; ko += 32) {
        __syncthreads();
#pragma unroll
        for (int t = 0; t < 2; t++) {
            int idx = tid + (t << 8);
            int r = idx >> 3, kq = idx & 7;
            float4 v = *(const float4*)(Abase + (size_t)(m0 + r)*BTL + ko + (kq << 2));
            STORE_A(AH, AL, r, kq, v)
        }
#pragma unroll
        for (int t = 0; t < 4; t++) {
            int idx = tid + (t << 8);
            int kr = idx >> 5, n = (idx & 31) << 2;
            float4 v = *(const float4*)(Bmat + (size_t)(ko + kr)*BTL + n);
            STORE_B(BH, BL, kr, n, v)
        }
        __syncthreads();
        MMA_CHUNK(AH, AL, BH, BL, d, warp_m, warp_n, lane)
    }
#pragma unroll
    for (int mt = 0; mt < 2; mt++)
#pragma unroll
        for (int nt = 0; nt < 4; nt++) {
            int row = warp_m*32 + mt*16 + (lane >> 2);
            int col = warp_n*32 + nt*8 + ((lane & 3) << 1);
            int r0 = m0 + row, r1 = r0 + 8;
            if (r0 < T)
                *(float2*)&Cout[((size_t)be*NN + r0)*BTL + col] = make_float2(d[mt][nt][0], d[mt][nt][1]);
            if (r1 < T)
                *(float2*)&Cout[((size_t)be*NN + r1)*BTL + col] = make_float2(d[mt][nt][2], d[mt][nt][3]);
        }
}

// ---------------- flash attention over gathered sequence (unchanged) -------
#define ATTN_SMEM ((128*68 + 128*68 + 64*68)*4)

__global__ void __launch_bounds__(256) attn_kernel() {
    int be = blockIdx.y;
    int qi = blockIdx.x;
    int T  = g_cnt[be];
    int q0 = qi << 6;
    if (q0 >= T) return;
    extern __shared__ float sm[];
    float* Qst = sm;
    float* KV  = sm + 128*68;
    float* Ps  = sm + 2*128*68;
    int tid = threadIdx.x;
    int ty = tid >> 4, tx = tid & 15;
    const float* Qg = g_q + (size_t)be*NN*BTL;
    const float* Kg = g_k + (size_t)be*NN*BTL;
    const float* Vg = g_v + (size_t)be*NN*BTL;

#pragma unroll
    for (int t2 = 0; t2 < 8; t2++) {
        int r  = (tid >> 3) + ((t2 & 1) << 5);
        int dq = (tid & 7) + ((t2 >> 1) << 3);
        float4 v = make_float4(0.f, 0.f, 0.f, 0.f);
        if (q0 + r < T) v = *(const float4*)(Qg + (size_t)(q0 + r)*BTL + (dq<<2));
        Qst[(dq*4+0)*68 + r] = v.x;
        Qst[(dq*4+1)*68 + r] = v.y;
        Qst[(dq*4+2)*68 + r] = v.z;
        Qst[(dq*4+3)*68 + r] = v.w;
    }
    float o[4][8];
#pragma unroll
    for (int i = 0; i < 4; i++)
#pragma unroll
        for (int c = 0; c < 8; c++) o[i][c] = 0.f;
    float mrow[4] = {-1e30f, -1e30f, -1e30f, -1e30f};
    float lrow[4] = {0.f, 0.f, 0.f, 0.f};
    const float scale = 0.088388347648318447f;

    for (int j = 0; j <= qi; j++) {
        int k0 = j << 6;
        __syncthreads();
#pragma unroll
        for (int t2 = 0; t2 < 8; t2++) {
            int r  = (tid >> 3) + ((t2 & 1) << 5);
            int dq = (tid & 7) + ((t2 >> 1) << 3);
            float4 v = make_float4(0.f, 0.f, 0.f, 0.f);
            if (k0 + r < T) v = *(const float4*)(Kg + (size_t)(k0 + r)*BTL + (dq<<2));
            KV[(dq*4+0)*68 + r] = v.x;
            KV[(dq*4+1)*68 + r] = v.y;
            KV[(dq*4+2)*68 + r] = v.z;
            KV[(dq*4+3)*68 + r] = v.w;
        }
        __syncthreads();
        float s[4][4];
#pragma unroll
        for (int i = 0; i < 4; i++)
#pragma unroll
            for (int jj = 0; jj < 4; jj++) s[i][jj] = 0.f;
#pragma unroll 4
        for (int d = 0; d < 128; d++) {
            float4 qa = *(const float4*)&Qst[d*68 + (ty<<2)];
            float4 ka = *(const float4*)&KV[d*68 + (tx<<2)];
            float av[4] = {qa.x, qa.y, qa.z, qa.w};
            float kv[4] = {ka.x, ka.y, ka.z, ka.w};
#pragma unroll
            for (int i = 0; i < 4; i++)
#pragma unroll
                for (int jj = 0; jj < 4; jj++) s[i][jj] += av[i]*kv[jj];
        }
#pragma unroll
        for (int i = 0; i < 4; i++) {
            int row = q0 + (ty<<2) + i;
            float pm = -1e30f;
#pragma unroll
            for (int jj = 0; jj < 4; jj++) {
                int col = k0 + (tx<<2) + jj;
                float sv = (col <= row && col < T) ? s[i][jj]*scale : -1e9f;
                s[i][jj] = sv;
                pm = fmaxf(pm, sv);
            }
            pm = fmaxf(pm, __shfl_xor_sync(0xffffffffu, pm, 8));
            pm = fmaxf(pm, __shfl_xor_sync(0xffffffffu, pm, 4));
            pm = fmaxf(pm, __shfl_xor_sync(0xffffffffu, pm, 2));
            pm = fmaxf(pm, __shfl_xor_sync(0xffffffffu, pm, 1));
            float newm = fmaxf(mrow[i], pm);
            float fac  = __expf(mrow[i] - newm);
            float rs = 0.f;
#pragma unroll
            for (int jj = 0; jj < 4; jj++) {
                float p = __expf(s[i][jj] - newm);
                s[i][jj] = p;
                rs += p;
            }
            rs += __shfl_xor_sync(0xffffffffu, rs, 8);
            rs += __shfl_xor_sync(0xffffffffu, rs, 4);
            rs += __shfl_xor_sync(0xffffffffu, rs, 2);
            rs += __shfl_xor_sync(0xffffffffu, rs, 1);
            lrow[i] = lrow[i]*fac + rs;
            mrow[i] = newm;
#pragma unroll
            for (int c = 0; c < 8; c++) o[i][c] *= fac;
#pragma unroll
            for (int jj = 0; jj < 4; jj++)
                Ps[((tx<<2)+jj)*68 + (ty<<2)+i] = s[i][jj];
        }
        __syncthreads();
#pragma unroll
        for (int t2 = 0; t2 < 8; t2++) {
            int r  = (tid >> 3) + ((t2 & 1) << 5);
            int dq = (tid & 7) + ((t2 >> 1) << 3);
            float4 v = make_float4(0.f, 0.f, 0.f, 0.f);
            if (k0 + r < T) v = *(const float4*)(Vg + (size_t)(k0 + r)*BTL + (dq<<2));
            *(float4*)&KV[r*128 + (dq<<2)] = v;
        }
        __syncthreads();
#pragma unroll 2
        for (int kk = 0; kk < 64; kk++) {
            float4 pv = *(const float4*)&Ps[kk*68 + (ty<<2)];
            float4 v0 = *(const float4*)&KV[kk*128 + (tx<<3)];
            float4 v1 = *(const float4*)&KV[kk*128 + (tx<<3) + 4];
            float pa[4] = {pv.x, pv.y, pv.z, pv.w};
            float vv[8] = {v0.x, v0.y, v0.z, v0.w, v1.x, v1.y, v1.z, v1.w};
#pragma unroll
            for (int i = 0; i < 4; i++)
#pragma unroll
                for (int c = 0; c < 8; c++) o[i][c] += pa[i]*vv[c];
        }
    }
#pragma unroll
    for (int i = 0; i < 4; i++) {
        int r = q0 + (ty<<2) + i;
        if (r < T) {
            float inv = 1.f / lrow[i];
            float* dst = g_o + ((size_t)be*NN + r)*BTL + (tx<<3);
            *(float4*)dst     = make_float4(o[i][0]*inv, o[i][1]*inv, o[i][2]*inv, o[i][3]*inv);
            *(float4*)(dst+4) = make_float4(o[i][4]*inv, o[i][5]*inv, o[i][6]*inv, o[i][7]*inv);
        }
    }
}

// ---------------- up: out += w * (o @ Wu[e]) ----------------
__global__ void __launch_bounds__(256) up_gemm(const float* __restrict__ Wu,
                                               float* __restrict__ out) {
    int be = blockIdx.y; int b = be >> 3, e = be & 7;
    int T  = g_cnt[be];
    int m0 = blockIdx.x << 6;
    if (m0 >= T) return;
    int col0 = blockIdx.z << 7;
    const float* Abase = g_o + (size_t)be*NN*BTL;
    const float* Bmat  = Wu + (size_t)e*BTL*DD;
    extern __shared__ float sm[];
    float* AH = sm;
    float* AL = sm + 2048;
    float* BH = sm + 4096;
    float* BL = sm + 8192;
    __shared__ int   rtok[64];
    __shared__ float rw[64];
    int tid = threadIdx.x, lane = tid & 31, wid = tid >> 5;
    int warp_m = wid >> 2, warp_n = wid & 3;
    if (tid < 64) {
        int r = m0 + tid;
        rtok[tid] = (r < T) ? g_list[be*NN + r] : 0;
        rw[tid]   = (r < T) ? g_wlist[be*NN + r] : 0.f;
    }
    float d[2][4][4];
#pragma unroll
    for (int mt = 0; mt < 2; mt++)
#pragma unroll
        for (int nt = 0; nt < 4; nt++)
#pragma unroll
            for (int i = 0; i < 4; i++) d[mt][nt][i] = 0.f;
    for (int ko = 0; ko < BTL; ko += 32) {
        __syncthreads();
#pragma unroll
        for (int t = 0; t < 2; t++) {
            int idx = tid + (t << 8);
            int r = idx >> 3, kq = idx & 7;
            float4 v = *(const float4*)(Abase + (size_t)(m0 + r)*BTL + ko + (kq << 2));
            STORE_A(AH, AL, r, kq, v)
        }
#pragma unroll
        for (int t = 0; t < 4; t++) {
            int idx = tid + (t << 8);
            int kr = idx >> 5, n = (idx & 31) << 2;
            float4 v = *(const float4*)(Bmat + (size_t)(ko + kr)*DD + col0 + n);
            STORE_B(BH, BL, kr, n, v)
        }
        __syncthreads();
        MMA_CHUNK(AH, AL, BH, BL, d, warp_m, warp_n, lane)
    }
#pragma unroll
    for (int mt = 0; mt < 2; mt++)
#pragma unroll
        for (int nt = 0; nt < 4; nt++) {
            int row = warp_m*32 + mt*16 + (lane >> 2);
            int col = warp_n*32 + nt*8 + ((lane & 3) << 1);
            int r0l = row, r1l = row + 8;
            if (m0 + r0l < T) {
                float w = rw[r0l];
                float* dst = out + ((size_t)b*NN + rtok[r0l])*DD + col0 + col;
                atomicAdd(dst,     w * d[mt][nt][0]);
                atomicAdd(dst + 1, w * d[mt][nt][1]);
            }
            if (m0 + r1l < T) {
                float w = rw[r1l];
                float* dst = out + ((size_t)b*NN + rtok[r1l])*DD + col0 + col;
                atomicAdd(dst,     w * d[mt][nt][2]);
                atomicAdd(dst + 1, w * d[mt][nt][3]);
            }
        }
}

// ---------------- scalars ----------------
__global__ void finalize(float* out, int out_size) {
    if (threadIdx.x == 0 && blockIdx.x == 0) {
        float denom = fmaxf(g_act, 1.f);
        float lbl = 0.f, fmaxv = 0.f;
#pragma unroll
        for (int e = 0; e < EE; e++) {
            float fr = g_fsum[e] / denom;
            float pm = g_psum[e] / denom;
            lbl += fr * pm;
            fmaxv = fmaxf(fmaxv, fr);
        }
        lbl *= (float)EE / (float)TOPK;
        float vio = fmaxv / ((float)TOPK / (float)EE) - 1.f;
        if (out_size >= BND + 2) {
            out[BND]     = lbl;
            out[BND + 1] = vio;
        }
    }
}

extern "C" void kernel_launch(void* const* d_in, const int* in_sizes, int n_in,
                              void* d_out, int out_size) {
    const float* x   = (const float*)d_in[0];
    const int*   act = (const int*)d_in[2];
    const float* Wg = (const float*)d_in[3];
    const float* Wd = (const float*)d_in[4];
    const float* Wq = (const float*)d_in[5];
    const float* Wk = (const float*)d_in[6];
    const float* Wv = (const float*)d_in[7];
    const float* Wu = (const float*)d_in[8];
    float* out = (float*)d_out;

    cudaFuncSetAttribute(down_gemm, cudaFuncAttributeMaxDynamicSharedMemorySize, GEMM_SMEM);
    cudaFuncSetAttribute(qkv_gemm,  cudaFuncAttributeMaxDynamicSharedMemorySize, GEMM_SMEM);
    cudaFuncSetAttribute(up_gemm,   cudaFuncAttributeMaxDynamicSharedMemorySize, GEMM_SMEM);
    cudaFuncSetAttribute(attn_kernel, cudaFuncAttributeMaxDynamicSharedMemorySize, ATTN_SMEM);

    cudaMemsetAsync(d_out, 0, (size_t)out_size * sizeof(float), 0);
    router_kernel<<<1024, 256>>>(x, Wg);
    router_reduce<<<1, 288>>>(act);
    build_lists<<<BE, 256>>>(act);
    dim3 g1(NN/64, BE);
    down_gemm<<<g1, 256, GEMM_SMEM>>>(x, Wd);
    dim3 g2(NN/64, BE, 3);
    qkv_gemm<<<g2, 256, GEMM_SMEM>>>(Wq, Wk, Wv);
    dim3 g3(NN/64, BE);
    attn_kernel<<<g3, 256, ATTN_SMEM>>>();
    dim3 g4(NN/64, BE, DD/128);
    up_gemm<<<g4, 256, GEMM_SMEM>>>(Wu, out);
    finalize<<<1, 32>>>(out, out_size);
}

// round 10
// speedup vs baseline: 1.5808x; 1.5808x over previous
#include <cuda_runtime.h>
#include <cstdint>

#define BB   4
#define NN   2048
#define DD   1024
#define EE   8
#define BTL  128
#define TOPK 2
#define BE   (BB*EE)
#define BND  (BB*NN*DD)
#define KSPLIT 2
#define KHALF (DD/KSPLIT)

// ---------------- static device scratch ----------------
__device__ int    g_list[BE*NN];
__device__ float  g_wlist[BE*NN];
__device__ int    g_cnt[BE];
__device__ int2   g_topi[BB*NN];
__device__ float2 g_w[BB*NN];
__device__ float  g_probs[BB*NN*EE];
__device__ float  g_psum[EE];
__device__ float  g_fsum[EE];
__device__ float  g_act;
__device__ float  g_h[(size_t)BE*NN*BTL];
__device__ float  g_h2[(size_t)BE*NN*BTL];
__device__ float  g_q[(size_t)BE*NN*BTL];
__device__ float  g_k[(size_t)BE*NN*BTL];
__device__ float  g_v[(size_t)BE*NN*BTL];
__device__ float  g_o[(size_t)BE*NN*BTL];

// ---------------- router: 1 warp per token ----------------
__global__ void __launch_bounds__(256) router_kernel(const float* __restrict__ x,
                                                     const float* __restrict__ Wg) {
    int token = (blockIdx.x * blockDim.x + threadIdx.x) >> 5;
    int lane  = threadIdx.x & 31;
    float acc[EE];
#pragma unroll
    for (int e = 0; e < EE; e++) acc[e] = 0.f;
    const float* xr = x + (size_t)token * DD;
    for (int d = lane; d < DD; d += 32) {
        float xv = xr[d];
        const float4 w0 = *(const float4*)(Wg + d*EE);
        const float4 w1 = *(const float4*)(Wg + d*EE + 4);
        acc[0] += xv*w0.x; acc[1] += xv*w0.y; acc[2] += xv*w0.z; acc[3] += xv*w0.w;
        acc[4] += xv*w1.x; acc[5] += xv*w1.y; acc[6] += xv*w1.z; acc[7] += xv*w1.w;
    }
#pragma unroll
    for (int off = 16; off; off >>= 1)
#pragma unroll
        for (int e = 0; e < EE; e++)
            acc[e] += __shfl_xor_sync(0xffffffffu, acc[e], off);
    if (lane == 0) {
        float m = acc[0];
#pragma unroll
        for (int e = 1; e < EE; e++) m = fmaxf(m, acc[e]);
        float p[EE], s = 0.f;
#pragma unroll
        for (int e = 0; e < EE; e++) { p[e] = expf(acc[e] - m); s += p[e]; }
        float inv = 1.f / s;
#pragma unroll
        for (int e = 0; e < EE; e++) { p[e] *= inv; g_probs[token*EE + e] = p[e]; }
        int i1 = 0; float v1 = p[0];
#pragma unroll
        for (int e = 1; e < EE; e++) if (p[e] > v1) { v1 = p[e]; i1 = e; }
        int i2 = -1; float v2 = -1.f;
#pragma unroll
        for (int e = 0; e < EE; e++) if (e != i1 && p[e] > v2) { v2 = p[e]; i2 = e; }
        float ws = v1 + v2;
        g_topi[token] = make_int2(i1, i2);
        g_w[token]    = make_float2(v1/ws, v2/ws);
    }
}

// ---------------- deterministic router stats ----------------
__global__ void router_reduce(const int* __restrict__ act) {
    int w = threadIdx.x >> 5, lane = threadIdx.x & 31;
    if (w < EE) {
        float ps = 0.f, fs = 0.f;
        for (int t = lane; t < BB*NN; t += 32) {
            float a = (act[t] != 0) ? 1.f : 0.f;
            ps += g_probs[t*EE + w] * a;
            int2 ti = g_topi[t];
            if (ti.x == w || ti.y == w) fs += a;
        }
#pragma unroll
        for (int off = 16; off; off >>= 1) {
            ps += __shfl_xor_sync(0xffffffffu, ps, off);
            fs += __shfl_xor_sync(0xffffffffu, fs, off);
        }
        if (lane == 0) { g_psum[w] = ps; g_fsum[w] = fs; }
    } else if (w == EE) {
        float s = 0.f;
        for (int t = lane; t < BB*NN; t += 32) s += (act[t] != 0) ? 1.f : 0.f;
#pragma unroll
        for (int off = 16; off; off >>= 1) s += __shfl_xor_sync(0xffffffffu, s, off);
        if (lane == 0) g_act = s;
    }
}

// ---------------- compact token lists per (b,e) ----------------
__global__ void build_lists(const int* __restrict__ act) {
    int be = blockIdx.x; int b = be >> 3, e = be & 7;
    __shared__ int s_scan[256];
    __shared__ int s_base;
    int tid = threadIdx.x;
    if (tid == 0) s_base = 0;
    __syncthreads();
    for (int c0 = 0; c0 < NN; c0 += 256) {
        int n = c0 + tid;
        int2 ti = g_topi[b*NN + n];
        int hit1 = (ti.x == e), hit2 = (ti.y == e);
        int f = ((hit1 || hit2) && (act[b*NN + n] != 0)) ? 1 : 0;
        s_scan[tid] = f;
        __syncthreads();
        int val = f;
        for (int off = 1; off < 256; off <<= 1) {
            int add = (tid >= off) ? s_scan[tid - off] : 0;
            __syncthreads();
            val += add;
            s_scan[tid] = val;
            __syncthreads();
        }
        if (f) {
            int pos = s_base + val - 1;
            g_list[be*NN + pos]  = n;
            float2 w = g_w[b*NN + n];
            g_wlist[be*NN + pos] = hit1 ? w.x : w.y;
        }
        __syncthreads();
        if (tid == 0) s_base += s_scan[255];
        __syncthreads();
    }
    if (tid == 0) g_cnt[be] = s_base;
}

// ---------------- GEMMs: 64x128 tile, 256 threads, 4x8 per thread ----------
// As: [32 k][68 rows pad], Bs: [32 k][128 cols]

// down split-K=2: z half writes g_h (z=0) or g_h2 (z=1); qkv sums on load.
__global__ void __launch_bounds__(256) down_gemm(const float* __restrict__ x,
                                                 const float* __restrict__ Wd) {
    int be = blockIdx.y; int b = be >> 3, e = be & 7;
    int T  = g_cnt[be];
    int m0 = blockIdx.x << 6;
    if (m0 >= T) return;
    int kz = blockIdx.z;
    float* Hout = (kz == 0) ? g_h : g_h2;
    __shared__ float As[32*68];
    __shared__ float Bs[32*128];
    __shared__ int   rtok[64];
    int tid = threadIdx.x;
    int ty = tid >> 4, tx = tid & 15;
    if (tid < 64) {
        int r = m0 + tid;
        rtok[tid] = (r < T) ? g_list[be*NN + r] : g_list[be*NN];
    }
    float acc[4][8];
#pragma unroll
    for (int i = 0; i < 4; i++)
#pragma unroll
        for (int j = 0; j < 8; j++) acc[i][j] = 0.f;
    const float* Wde = Wd + (size_t)e * DD * BTL;
    int kbeg = kz * KHALF, kend = kbeg + KHALF;
    for (int ko = kbeg; ko < kend; ko += 32) {
        __syncthreads();
#pragma unroll
        for (int t2 = 0; t2 < 2; t2++) {
            int task = tid + (t2 << 8);
            int r = task >> 3, kq = task & 7;
            const float4 v = *(const float4*)(x + (size_t)(b*NN + rtok[r])*DD + ko + (kq<<2));
            As[(kq*4+0)*68 + r] = v.x;
            As[(kq*4+1)*68 + r] = v.y;
            As[(kq*4+2)*68 + r] = v.z;
            As[(kq*4+3)*68 + r] = v.w;
        }
#pragma unroll
        for (int t2 = 0; t2 < 4; t2++) {
            int task = tid + (t2 << 8);
            int kr = task >> 5, cq = task & 31;
            *(float4*)&Bs[kr*128 + (cq<<2)] =
                *(const float4*)(Wde + (size_t)(ko + kr)*BTL + (cq<<2));
        }
        __syncthreads();
#pragma unroll
        for (int kk = 0; kk < 32; kk++) {
            float4 a  = *(const float4*)&As[kk*68 + (ty<<2)];
            float4 b0 = *(const float4*)&Bs[kk*128 + (tx<<3)];
            float4 b1 = *(const float4*)&Bs[kk*128 + (tx<<3) + 4];
            float av[4] = {a.x, a.y, a.z, a.w};
            float bv[8] = {b0.x, b0.y, b0.z, b0.w, b1.x, b1.y, b1.z, b1.w};
#pragma unroll
            for (int i = 0; i < 4; i++)
#pragma unroll
                for (int j = 0; j < 8; j++) acc[i][j] += av[i]*bv[j];
        }
    }
#pragma unroll
    for (int i = 0; i < 4; i++) {
        int r = m0 + (ty<<2) + i;
        if (r < T) {
            float* dst = Hout + ((size_t)be*NN + r)*BTL + (tx<<3);
            *(float4*)dst     = make_float4(acc[i][0], acc[i][1], acc[i][2], acc[i][3]);
            *(float4*)(dst+4) = make_float4(acc[i][4], acc[i][5], acc[i][6], acc[i][7]);
        }
    }
}

__global__ void __launch_bounds__(256) qkv_gemm(const float* __restrict__ Wq,
                                                const float* __restrict__ Wk,
                                                const float* __restrict__ Wv) {
    int be = blockIdx.y; int e = be & 7;
    int T  = g_cnt[be];
    int m0 = blockIdx.x << 6;
    if (m0 >= T) return;
    int z = blockIdx.z;
    const float* Bmat = ((z == 0) ? Wq : (z == 1) ? Wk : Wv) + (size_t)e*BTL*BTL;
    float* Cout = (z == 0) ? g_q : (z == 1) ? g_k : g_v;
    const float* Abase  = g_h  + (size_t)be*NN*BTL;
    const float* Abase2 = g_h2 + (size_t)be*NN*BTL;
    __shared__ float As[32*68];
    __shared__ float Bs[32*128];
    int tid = threadIdx.x;
    int ty = tid >> 4, tx = tid & 15;
    float acc[4][8];
#pragma unroll
    for (int i = 0; i < 4; i++)
#pragma unroll
        for (int j = 0; j < 8; j++) acc[i][j] = 0.f;
    for (int ko = 0; ko < BTL; ko += 32) {
        __syncthreads();
#pragma unroll
        for (int t2 = 0; t2 < 2; t2++) {
            int task = tid + (t2 << 8);
            int r = task >> 3, kq = task & 7;
            size_t off = (size_t)(m0 + r)*BTL + ko + (kq<<2);
            const float4 v1 = *(const float4*)(Abase  + off);
            const float4 v2 = *(const float4*)(Abase2 + off);
            As[(kq*4+0)*68 + r] = v1.x + v2.x;
            As[(kq*4+1)*68 + r] = v1.y + v2.y;
            As[(kq*4+2)*68 + r] = v1.z + v2.z;
            As[(kq*4+3)*68 + r] = v1.w + v2.w;
        }
#pragma unroll
        for (int t2 = 0; t2 < 4; t2++) {
            int task = tid + (t2 << 8);
            int kr = task >> 5, cq = task & 31;
            *(float4*)&Bs[kr*128 + (cq<<2)] =
                *(const float4*)(Bmat + (size_t)(ko + kr)*BTL + (cq<<2));
        }
        __syncthreads();
#pragma unroll
        for (int kk = 0; kk < 32; kk++) {
            float4 a  = *(const float4*)&As[kk*68 + (ty<<2)];
            float4 b0 = *(const float4*)&Bs[kk*128 + (tx<<3)];
            float4 b1 = *(const float4*)&Bs[kk*128 + (tx<<3) + 4];
            float av[4] = {a.x, a.y, a.z, a.w};
            float bv[8] = {b0.x, b0.y, b0.z, b0.w, b1.x, b1.y, b1.z, b1.w};
#pragma unroll
            for (int i = 0; i < 4; i++)
#pragma unroll
                for (int j = 0; j < 8; j++) acc[i][j] += av[i]*bv[j];
        }
    }
#pragma unroll
    for (int i = 0; i < 4; i++) {
        int r = m0 + (ty<<2) + i;
        if (r < T) {
            float* dst = Cout + ((size_t)be*NN + r)*BTL + (tx<<3);
            *(float4*)dst     = make_float4(acc[i][0], acc[i][1], acc[i][2], acc[i][3]);
            *(float4*)(dst+4) = make_float4(acc[i][4], acc[i][5], acc[i][6], acc[i][7]);
        }
    }
}

// ---------------- flash attention over gathered sequence ----------------
#define ATTN_SMEM ((128*68 + 128*68 + 64*68)*4)

__global__ void __launch_bounds__(256) attn_kernel() {
    int be = blockIdx.y;
    int qi = blockIdx.x;
    int T  = g_cnt[be];
    int q0 = qi << 6;
    if (q0 >= T) return;
    extern __shared__ float sm[];
    float* Qst = sm;
    float* KV  = sm + 128*68;
    float* Ps  = sm + 2*128*68;
    int tid = threadIdx.x;
    int ty = tid >> 4, tx = tid & 15;
    const float* Qg = g_q + (size_t)be*NN*BTL;
    const float* Kg = g_k + (size_t)be*NN*BTL;
    const float* Vg = g_v + (size_t)be*NN*BTL;

#pragma unroll
    for (int t2 = 0; t2 < 8; t2++) {
        int r  = (tid >> 3) + ((t2 & 1) << 5);
        int dq = (tid & 7) + ((t2 >> 1) << 3);
        float4 v = make_float4(0.f, 0.f, 0.f, 0.f);
        if (q0 + r < T) v = *(const float4*)(Qg + (size_t)(q0 + r)*BTL + (dq<<2));
        Qst[(dq*4+0)*68 + r] = v.x;
        Qst[(dq*4+1)*68 + r] = v.y;
        Qst[(dq*4+2)*68 + r] = v.z;
        Qst[(dq*4+3)*68 + r] = v.w;
    }
    float o[4][8];
#pragma unroll
    for (int i = 0; i < 4; i++)
#pragma unroll
        for (int c = 0; c < 8; c++) o[i][c] = 0.f;
    float mrow[4] = {-1e30f, -1e30f, -1e30f, -1e30f};
    float lrow[4] = {0.f, 0.f, 0.f, 0.f};
    const float scale = 0.088388347648318447f;

    for (int j = 0; j <= qi; j++) {
        int k0 = j << 6;
        __syncthreads();
#pragma unroll
        for (int t2 = 0; t2 < 8; t2++) {
            int r  = (tid >> 3) + ((t2 & 1) << 5);
            int dq = (tid & 7) + ((t2 >> 1) << 3);
            float4 v = make_float4(0.f, 0.f, 0.f, 0.f);
            if (k0 + r < T) v = *(const float4*)(Kg + (size_t)(k0 + r)*BTL + (dq<<2));
            KV[(dq*4+0)*68 + r] = v.x;
            KV[(dq*4+1)*68 + r] = v.y;
            KV[(dq*4+2)*68 + r] = v.z;
            KV[(dq*4+3)*68 + r] = v.w;
        }
        __syncthreads();
        float s[4][4];
#pragma unroll
        for (int i = 0; i < 4; i++)
#pragma unroll
            for (int jj = 0; jj < 4; jj++) s[i][jj] = 0.f;
#pragma unroll 4
        for (int d = 0; d < 128; d++) {
            float4 qa = *(const float4*)&Qst[d*68 + (ty<<2)];
            float4 ka = *(const float4*)&KV[d*68 + (tx<<2)];
            float av[4] = {qa.x, qa.y, qa.z, qa.w};
            float kv[4] = {ka.x, ka.y, ka.z, ka.w};
#pragma unroll
            for (int i = 0; i < 4; i++)
#pragma unroll
                for (int jj = 0; jj < 4; jj++) s[i][jj] += av[i]*kv[jj];
        }
#pragma unroll
        for (int i = 0; i < 4; i++) {
            int row = q0 + (ty<<2) + i;
            float pm = -1e30f;
#pragma unroll
            for (int jj = 0; jj < 4; jj++) {
                int col = k0 + (tx<<2) + jj;
                float sv = (col <= row && col < T) ? s[i][jj]*scale : -1e9f;
                s[i][jj] = sv;
                pm = fmaxf(pm, sv);
            }
            pm = fmaxf(pm, __shfl_xor_sync(0xffffffffu, pm, 8));
            pm = fmaxf(pm, __shfl_xor_sync(0xffffffffu, pm, 4));
            pm = fmaxf(pm, __shfl_xor_sync(0xffffffffu, pm, 2));
            pm = fmaxf(pm, __shfl_xor_sync(0xffffffffu, pm, 1));
            float newm = fmaxf(mrow[i], pm);
            float fac  = __expf(mrow[i] - newm);
            float rs = 0.f;
#pragma unroll
            for (int jj = 0; jj < 4; jj++) {
                float p = __expf(s[i][jj] - newm);
                s[i][jj] = p;
                rs += p;
            }
            rs += __shfl_xor_sync(0xffffffffu, rs, 8);
            rs += __shfl_xor_sync(0xffffffffu, rs, 4);
            rs += __shfl_xor_sync(0xffffffffu, rs, 2);
            rs += __shfl_xor_sync(0xffffffffu, rs, 1);
            lrow[i] = lrow[i]*fac + rs;
            mrow[i] = newm;
#pragma unroll
            for (int c = 0; c < 8; c++) o[i][c] *= fac;
#pragma unroll
            for (int jj = 0; jj < 4; jj++)
                Ps[((tx<<2)+jj)*68 + (ty<<2)+i] = s[i][jj];
        }
        __syncthreads();
#pragma unroll
        for (int t2 = 0; t2 < 8; t2++) {
            int r  = (tid >> 3) + ((t2 & 1) << 5);
            int dq = (tid & 7) + ((t2 >> 1) << 3);
            float4 v = make_float4(0.f, 0.f, 0.f, 0.f);
            if (k0 + r < T) v = *(const float4*)(Vg + (size_t)(k0 + r)*BTL + (dq<<2));
            *(float4*)&KV[r*128 + (dq<<2)] = v;
        }
        __syncthreads();
#pragma unroll 2
        for (int kk = 0; kk < 64; kk++) {
            float4 pv = *(const float4*)&Ps[kk*68 + (ty<<2)];
            float4 v0 = *(const float4*)&KV[kk*128 + (tx<<3)];
            float4 v1 = *(const float4*)&KV[kk*128 + (tx<<3) + 4];
            float pa[4] = {pv.x, pv.y, pv.z, pv.w};
            float vv[8] = {v0.x, v0.y, v0.z, v0.w, v1.x, v1.y, v1.z, v1.w};
#pragma unroll
            for (int i = 0; i < 4; i++)
#pragma unroll
                for (int c = 0; c < 8; c++) o[i][c] += pa[i]*vv[c];
        }
    }
#pragma unroll
    for (int i = 0; i < 4; i++) {
        int r = q0 + (ty<<2) + i;
        if (r < T) {
            float inv = 1.f / lrow[i];
            float* dst = g_o + ((size_t)be*NN + r)*BTL + (tx<<3);
            *(float4*)dst     = make_float4(o[i][0]*inv, o[i][1]*inv, o[i][2]*inv, o[i][3]*inv);
            *(float4*)(dst+4) = make_float4(o[i][4]*inv, o[i][5]*inv, o[i][6]*inv, o[i][7]*inv);
        }
    }
}

// ---------------- up-proj + weighted combine ----------------
__global__ void __launch_bounds__(256) up_gemm(const float* __restrict__ Wu,
                                               float* __restrict__ out) {
    int be = blockIdx.y; int b = be >> 3, e = be & 7;
    int T  = g_cnt[be];
    int m0 = blockIdx.x << 6;
    if (m0 >= T) return;
    int col0 = blockIdx.z << 7;
    const float* Abase = g_o + (size_t)be*NN*BTL;
    const float* Bmat  = Wu + (size_t)e*BTL*DD;
    __shared__ float As[32*68];
    __shared__ float Bs[32*128];
    __shared__ int   rtok[64];
    __shared__ float rw[64];
    int tid = threadIdx.x;
    int ty = tid >> 4, tx = tid & 15;
    if (tid < 64) {
        int r = m0 + tid;
        rtok[tid] = (r < T) ? g_list[be*NN + r] : 0;
        rw[tid]   = (r < T) ? g_wlist[be*NN + r] : 0.f;
    }
    float acc[4][8];
#pragma unroll
    for (int i = 0; i < 4; i++)
#pragma unroll
        for (int j = 0; j < 8; j++) acc[i][j] = 0.f;
    for (int ko = 0; ko < BTL; ko += 32) {
        __syncthreads();
#pragma unroll
        for (int t2 = 0; t2 < 2; t2++) {
            int task = tid + (t2 << 8);
            int r = task >> 3, kq = task & 7;
            const float4 v = *(const float4*)(Abase + (size_t)(m0 + r)*BTL + ko + (kq<<2));
            As[(kq*4+0)*68 + r] = v.x;
            As[(kq*4+1)*68 + r] = v.y;
            As[(kq*4+2)*68 + r] = v.z;
            As[(kq*4+3)*68 + r] = v.w;
        }
#pragma unroll
        for (int t2 = 0; t2 < 4; t2++) {
            int task = tid + (t2 << 8);
            int kr = task >> 5, cq = task & 31;
            *(float4*)&Bs[kr*128 + (cq<<2)] =
                *(const float4*)(Bmat + (size_t)(ko + kr)*DD + col0 + (cq<<2));
        }
        __syncthreads();
#pragma unroll
        for (int kk = 0; kk < 32; kk++) {
            float4 a  = *(const float4*)&As[kk*68 + (ty<<2)];
            float4 b0 = *(const float4*)&Bs[kk*128 + (tx<<3)];
            float4 b1 = *(const float4*)&Bs[kk*128 + (tx<<3) + 4];
            float av[4] = {a.x, a.y, a.z, a.w};
            float bv[8] = {b0.x, b0.y, b0.z, b0.w, b1.x, b1.y, b1.z, b1.w};
#pragma unroll
            for (int i = 0; i < 4; i++)
#pragma unroll
                for (int j = 0; j < 8; j++) acc[i][j] += av[i]*bv[j];
        }
    }
#pragma unroll
    for (int i = 0; i < 4; i++) {
        int r = m0 + (ty<<2) + i;
        if (r < T) {
            int   tok = rtok[(ty<<2)+i];
            float w   = rw[(ty<<2)+i];
            float* dst = out + ((size_t)b*NN + tok)*DD + col0 + (tx<<3);
#pragma unroll
            for (int j = 0; j < 8; j++)
                atomicAdd(dst + j, w * acc[i][j]);
        }
    }
}

// ---------------- scalars ----------------
__global__ void finalize(float* out, int out_size) {
    if (threadIdx.x == 0 && blockIdx.x == 0) {
        float denom = fmaxf(g_act, 1.f);
        float lbl = 0.f, fmaxv = 0.f;
#pragma unroll
        for (int e = 0; e < EE; e++) {
            float fr = g_fsum[e] / denom;
            float pm = g_psum[e] / denom;
            lbl += fr * pm;
            fmaxv = fmaxf(fmaxv, fr);
        }
        lbl *= (float)EE / (float)TOPK;
        float vio = fmaxv / ((float)TOPK / (float)EE) - 1.f;
        if (out_size >= BND + 2) {
            out[BND]     = lbl;
            out[BND + 1] = vio;
        }
    }
}

extern "C" void kernel_launch(void* const* d_in, const int* in_sizes, int n_in,
                              void* d_out, int out_size) {
    const float* x   = (const float*)d_in[0];
    const int*   act = (const int*)d_in[2];
    const float* Wg = (const float*)d_in[3];
    const float* Wd = (const float*)d_in[4];
    const float* Wq = (const float*)d_in[5];
    const float* Wk = (const float*)d_in[6];
    const float* Wv = (const float*)d_in[7];
    const float* Wu = (const float*)d_in[8];
    float* out = (float*)d_out;

    cudaMemsetAsync(d_out, 0, (size_t)out_size * sizeof(float), 0);
    router_kernel<<<1024, 256>>>(x, Wg);
    router_reduce<<<1, 288>>>(act);
    build_lists<<<BE, 256>>>(act);
    dim3 g1(NN/64, BE, KSPLIT);
    down_gemm<<<g1, 256>>>(x, Wd);
    dim3 g2(NN/64, BE, 3);
    qkv_gemm<<<g2, 256>>>(Wq, Wk, Wv);
    cudaFuncSetAttribute(attn_kernel, cudaFuncAttributeMaxDynamicSharedMemorySize, ATTN_SMEM);
    dim3 g3(NN/64, BE);
    attn_kernel<<<g3, 256, ATTN_SMEM>>>();
    dim3 g4(NN/64, BE, DD/128);
    up_gemm<<<g4, 256>>>(Wu, out);
    finalize<<<1, 32>>>(out, out_size);
}

// round 13
// speedup vs baseline: 1.9044x; 1.2047x over previous
#include <cuda_runtime.h>
#include <cstdint>

#define BB   4
#define NN   2048
#define DD   1024
#define EE   8
#define BTL  128
#define TOPK 2
#define BE   (BB*EE)
#define BND  (BB*NN*DD)
#define KSPLIT 2
#define KHALF (DD/KSPLIT)

// ---------------- static device scratch ----------------
__device__ int    g_list[BE*NN];
__device__ float  g_wlist[BE*NN];
__device__ int    g_cnt[BE];
__device__ int2   g_topi[BB*NN];
__device__ float2 g_w[BB*NN];
__device__ float  g_probs[BB*NN*EE];
__device__ float  g_psum[EE];
__device__ float  g_fsum[EE];
__device__ float  g_act;
__device__ float  g_h[(size_t)BE*NN*BTL];
__device__ float  g_h2[(size_t)BE*NN*BTL];
__device__ float  g_q[(size_t)BE*NN*BTL];
__device__ float  g_k[(size_t)BE*NN*BTL];
__device__ float  g_v[(size_t)BE*NN*BTL];
__device__ float  g_o[(size_t)BE*NN*BTL];

// ---------------- router: 1 warp per token ----------------
__global__ void __launch_bounds__(256) router_kernel(const float* __restrict__ x,
                                                     const float* __restrict__ Wg) {
    int token = (blockIdx.x * blockDim.x + threadIdx.x) >> 5;
    int lane  = threadIdx.x & 31;
    float acc[EE];
#pragma unroll
    for (int e = 0; e < EE; e++) acc[e] = 0.f;
    const float* xr = x + (size_t)token * DD;
    for (int d = lane; d < DD; d += 32) {
        float xv = xr[d];
        const float4 w0 = *(const float4*)(Wg + d*EE);
        const float4 w1 = *(const float4*)(Wg + d*EE + 4);
        acc[0] += xv*w0.x; acc[1] += xv*w0.y; acc[2] += xv*w0.z; acc[3] += xv*w0.w;
        acc[4] += xv*w1.x; acc[5] += xv*w1.y; acc[6] += xv*w1.z; acc[7] += xv*w1.w;
    }
#pragma unroll
    for (int off = 16; off; off >>= 1)
#pragma unroll
        for (int e = 0; e < EE; e++)
            acc[e] += __shfl_xor_sync(0xffffffffu, acc[e], off);
    if (lane == 0) {
        float m = acc[0];
#pragma unroll
        for (int e = 1; e < EE; e++) m = fmaxf(m, acc[e]);
        float p[EE], s = 0.f;
#pragma unroll
        for (int e = 0; e < EE; e++) { p[e] = expf(acc[e] - m); s += p[e]; }
        float inv = 1.f / s;
#pragma unroll
        for (int e = 0; e < EE; e++) { p[e] *= inv; g_probs[token*EE + e] = p[e]; }
        int i1 = 0; float v1 = p[0];
#pragma unroll
        for (int e = 1; e < EE; e++) if (p[e] > v1) { v1 = p[e]; i1 = e; }
        int i2 = -1; float v2 = -1.f;
#pragma unroll
        for (int e = 0; e < EE; e++) if (e != i1 && p[e] > v2) { v2 = p[e]; i2 = e; }
        float ws = v1 + v2;
        g_topi[token] = make_int2(i1, i2);
        g_w[token]    = make_float2(v1/ws, v2/ws);
    }
}

// ---------------- deterministic router stats ----------------
__global__ void router_reduce(const int* __restrict__ act) {
    int w = threadIdx.x >> 5, lane = threadIdx.x & 31;
    if (w < EE) {
        float ps = 0.f, fs = 0.f;
        for (int t = lane; t < BB*NN; t += 32) {
            float a = (act[t] != 0) ? 1.f : 0.f;
            ps += g_probs[t*EE + w] * a;
            int2 ti = g_topi[t];
            if (ti.x == w || ti.y == w) fs += a;
        }
#pragma unroll
        for (int off = 16; off; off >>= 1) {
            ps += __shfl_xor_sync(0xffffffffu, ps, off);
            fs += __shfl_xor_sync(0xffffffffu, fs, off);
        }
        if (lane == 0) { g_psum[w] = ps; g_fsum[w] = fs; }
    } else if (w == EE) {
        float s = 0.f;
        for (int t = lane; t < BB*NN; t += 32) s += (act[t] != 0) ? 1.f : 0.f;
#pragma unroll
        for (int off = 16; off; off >>= 1) s += __shfl_xor_sync(0xffffffffu, s, off);
        if (lane == 0) g_act = s;
    }
}

// ---------------- compact token lists per (b,e) ----------------
__global__ void build_lists(const int* __restrict__ act) {
    int be = blockIdx.x; int b = be >> 3, e = be & 7;
    __shared__ int s_scan[256];
    __shared__ int s_base;
    int tid = threadIdx.x;
    if (tid == 0) s_base = 0;
    __syncthreads();
    for (int c0 = 0; c0 < NN; c0 += 256) {
        int n = c0 + tid;
        int2 ti = g_topi[b*NN + n];
        int hit1 = (ti.x == e), hit2 = (ti.y == e);
        int f = ((hit1 || hit2) && (act[b*NN + n] != 0)) ? 1 : 0;
        s_scan[tid] = f;
        __syncthreads();
        int val = f;
        for (int off = 1; off < 256; off <<= 1) {
            int add = (tid >= off) ? s_scan[tid - off] : 0;
            __syncthreads();
            val += add;
            s_scan[tid] = val;
            __syncthreads();
        }
        if (f) {
            int pos = s_base + val - 1;
            g_list[be*NN + pos]  = n;
            float2 w = g_w[b*NN + n];
            g_wlist[be*NN + pos] = hit1 ? w.x : w.y;
        }
        __syncthreads();
        if (tid == 0) s_base += s_scan[255];
        __syncthreads();
    }
    if (tid == 0) g_cnt[be] = s_base;
}

// ---------------- GEMMs: 64x128 tile, 128 threads, 8x8 per thread ----------
// As: [32 k][68 rows pad], Bs: [32 k][128 cols]
// thread map: ty = tid>>4 (0..7) -> rows ty*8..+8 ; tx = tid&15 -> cols tx*8..+8

#define GEMM_MAIN(As, Bs, acc)                                                  \
    _Pragma("unroll 8")                                                         \
    for (int kk = 0; kk < 32; kk++) {                                           \
        float4 a0 = *(const float4*)&(As)[kk*68 + (ty<<3)];                     \
        float4 a1 = *(const float4*)&(As)[kk*68 + (ty<<3) + 4];                 \
        float4 b0 = *(const float4*)&(Bs)[kk*128 + (tx<<3)];                    \
        float4 b1 = *(const float4*)&(Bs)[kk*128 + (tx<<3) + 4];                \
        float av[8] = {a0.x, a0.y, a0.z, a0.w, a1.x, a1.y, a1.z, a1.w};         \
        float bv[8] = {b0.x, b0.y, b0.z, b0.w, b1.x, b1.y, b1.z, b1.w};         \
        _Pragma("unroll")                                                       \
        for (int i = 0; i < 8; i++)                                             \
            _Pragma("unroll")                                                   \
            for (int j = 0; j < 8; j++) (acc)[i][j] += av[i]*bv[j];             \
    }

// down split-K=2: z half writes g_h (z=0) or g_h2 (z=1); qkv sums on load.
__global__ void __launch_bounds__(128) down_gemm(const float* __restrict__ x,
                                                 const float* __restrict__ Wd) {
    int be = blockIdx.y; int b = be >> 3, e = be & 7;
    int T  = g_cnt[be];
    int m0 = blockIdx.x << 6;
    if (m0 >= T) return;
    int kz = blockIdx.z;
    float* Hout = (kz == 0) ? g_h : g_h2;
    __shared__ float As[32*68];
    __shared__ float Bs[32*128];
    __shared__ int   rtok[64];
    int tid = threadIdx.x;
    int ty = tid >> 4, tx = tid & 15;
    if (tid < 64) {
        int r = m0 + tid;
        rtok[tid] = (r < T) ? g_list[be*NN + r] : g_list[be*NN];
    }
    float acc[8][8];
#pragma unroll
    for (int i = 0; i < 8; i++)
#pragma unroll
        for (int j = 0; j < 8; j++) acc[i][j] = 0.f;
    const float* Wde = Wd + (size_t)e * DD * BTL;
    int kbeg = kz * KHALF, kend = kbeg + KHALF;
    for (int ko = kbeg; ko < kend; ko += 32) {
        __syncthreads();
#pragma unroll
        for (int t2 = 0; t2 < 4; t2++) {
            int task = tid + (t2 << 7);
            int r = task >> 3, kq = task & 7;
            const float4 v = *(const float4*)(x + (size_t)(b*NN + rtok[r])*DD + ko + (kq<<2));
            As[(kq*4+0)*68 + r] = v.x;
            As[(kq*4+1)*68 + r] = v.y;
            As[(kq*4+2)*68 + r] = v.z;
            As[(kq*4+3)*68 + r] = v.w;
        }
#pragma unroll
        for (int t2 = 0; t2 < 8; t2++) {
            int task = tid + (t2 << 7);
            int kr = task >> 5, cq = task & 31;
            *(float4*)&Bs[kr*128 + (cq<<2)] =
                *(const float4*)(Wde + (size_t)(ko + kr)*BTL + (cq<<2));
        }
        __syncthreads();
        GEMM_MAIN(As, Bs, acc)
    }
#pragma unroll
    for (int i = 0; i < 8; i++) {
        int r = m0 + (ty<<3) + i;
        if (r < T) {
            float* dst = Hout + ((size_t)be*NN + r)*BTL + (tx<<3);
            *(float4*)dst     = make_float4(acc[i][0], acc[i][1], acc[i][2], acc[i][3]);
            *(float4*)(dst+4) = make_float4(acc[i][4], acc[i][5], acc[i][6], acc[i][7]);
        }
    }
}

__global__ void __launch_bounds__(128) qkv_gemm(const float* __restrict__ Wq,
                                                const float* __restrict__ Wk,
                                                const float* __restrict__ Wv) {
    int be = blockIdx.y; int e = be & 7;
    int T  = g_cnt[be];
    int m0 = blockIdx.x << 6;
    if (m0 >= T) return;
    int z = blockIdx.z;
    const float* Bmat = ((z == 0) ? Wq : (z == 1) ? Wk : Wv) + (size_t)e*BTL*BTL;
    float* Cout = (z == 0) ? g_q : (z == 1) ? g_k : g_v;
    const float* Abase  = g_h  + (size_t)be*NN*BTL;
    const float* Abase2 = g_h2 + (size_t)be*NN*BTL;
    __shared__ float As[32*68];
    __shared__ float Bs[32*128];
    int tid = threadIdx.x;
    int ty = tid >> 4, tx = tid & 15;
    float acc[8][8];
#pragma unroll
    for (int i = 0; i < 8; i++)
#pragma unroll
        for (int j = 0; j < 8; j++) acc[i][j] = 0.f;
    for (int ko = 0; ko < BTL; ko += 32) {
        __syncthreads();
#pragma unroll
        for (int t2 = 0; t2 < 4; t2++) {
            int task = tid + (t2 << 7);
            int r = task >> 3, kq = task & 7;
            size_t off = (size_t)(m0 + r)*BTL + ko + (kq<<2);
            const float4 v1 = *(const float4*)(Abase  + off);
            const float4 v2 = *(const float4*)(Abase2 + off);
            As[(kq*4+0)*68 + r] = v1.x + v2.x;
            As[(kq*4+1)*68 + r] = v1.y + v2.y;
            As[(kq*4+2)*68 + r] = v1.z + v2.z;
            As[(kq*4+3)*68 + r] = v1.w + v2.w;
        }
#pragma unroll
        for (int t2 = 0; t2 < 8; t2++) {
            int task = tid + (t2 << 7);
            int kr = task >> 5, cq = task & 31;
            *(float4*)&Bs[kr*128 + (cq<<2)] =
                *(const float4*)(Bmat + (size_t)(ko + kr)*BTL + (cq<<2));
        }
        __syncthreads();
        GEMM_MAIN(As, Bs, acc)
    }
#pragma unroll
    for (int i = 0; i < 8; i++) {
        int r = m0 + (ty<<3) + i;
        if (r < T) {
            float* dst = Cout + ((size_t)be*NN + r)*BTL + (tx<<3);
            *(float4*)dst     = make_float4(acc[i][0], acc[i][1], acc[i][2], acc[i][3]);
            *(float4*)(dst+4) = make_float4(acc[i][4], acc[i][5], acc[i][6], acc[i][7]);
        }
    }
}

// ---------------- flash attention over gathered sequence (unchanged) ------
#define ATTN_SMEM ((128*68 + 128*68 + 64*68)*4)

__global__ void __launch_bounds__(256) attn_kernel() {
    int be = blockIdx.y;
    int qi = blockIdx.x;
    int T  = g_cnt[be];
    int q0 = qi << 6;
    if (q0 >= T) return;
    extern __shared__ float sm[];
    float* Qst = sm;
    float* KV  = sm + 128*68;
    float* Ps  = sm + 2*128*68;
    int tid = threadIdx.x;
    int ty = tid >> 4, tx = tid & 15;
    const float* Qg = g_q + (size_t)be*NN*BTL;
    const float* Kg = g_k + (size_t)be*NN*BTL;
    const float* Vg = g_v + (size_t)be*NN*BTL;

#pragma unroll
    for (int t2 = 0; t2 < 8; t2++) {
        int r  = (tid >> 3) + ((t2 & 1) << 5);
        int dq = (tid & 7) + ((t2 >> 1) << 3);
        float4 v = make_float4(0.f, 0.f, 0.f, 0.f);
        if (q0 + r < T) v = *(const float4*)(Qg + (size_t)(q0 + r)*BTL + (dq<<2));
        Qst[(dq*4+0)*68 + r] = v.x;
        Qst[(dq*4+1)*68 + r] = v.y;
        Qst[(dq*4+2)*68 + r] = v.z;
        Qst[(dq*4+3)*68 + r] = v.w;
    }
    float o[4][8];
#pragma unroll
    for (int i = 0; i < 4; i++)
#pragma unroll
        for (int c = 0; c < 8; c++) o[i][c] = 0.f;
    float mrow[4] = {-1e30f, -1e30f, -1e30f, -1e30f};
    float lrow[4] = {0.f, 0.f, 0.f, 0.f};
    const float scale = 0.088388347648318447f;

    for (int j = 0; j <= qi; j++) {
        int k0 = j << 6;
        __syncthreads();
#pragma unroll
        for (int t2 = 0; t2 < 8; t2++) {
            int r  = (tid >> 3) + ((t2 & 1) << 5);
            int dq = (tid & 7) + ((t2 >> 1) << 3);
            float4 v = make_float4(0.f, 0.f, 0.f, 0.f);
            if (k0 + r < T) v = *(const float4*)(Kg + (size_t)(k0 + r)*BTL + (dq<<2));
            KV[(dq*4+0)*68 + r] = v.x;
            KV[(dq*4+1)*68 + r] = v.y;
            KV[(dq*4+2)*68 + r] = v.z;
            KV[(dq*4+3)*68 + r] = v.w;
        }
        __syncthreads();
        float s[4][4];
#pragma unroll
        for (int i = 0; i < 4; i++)
#pragma unroll
            for (int jj = 0; jj < 4; jj++) s[i][jj] = 0.f;
#pragma unroll 4
        for (int d = 0; d < 128; d++) {
            float4 qa = *(const float4*)&Qst[d*68 + (ty<<2)];
            float4 ka = *(const float4*)&KV[d*68 + (tx<<2)];
            float av[4] = {qa.x, qa.y, qa.z, qa.w};
            float kv[4] = {ka.x, ka.y, ka.z, ka.w};
#pragma unroll
            for (int i = 0; i < 4; i++)
#pragma unroll
                for (int jj = 0; jj < 4; jj++) s[i][jj] += av[i]*kv[jj];
        }
#pragma unroll
        for (int i = 0; i < 4; i++) {
            int row = q0 + (ty<<2) + i;
            float pm = -1e30f;
#pragma unroll
            for (int jj = 0; jj < 4; jj++) {
                int col = k0 + (tx<<2) + jj;
                float sv = (col <= row && col < T) ? s[i][jj]*scale : -1e9f;
                s[i][jj] = sv;
                pm = fmaxf(pm, sv);
            }
            pm = fmaxf(pm, __shfl_xor_sync(0xffffffffu, pm, 8));
            pm = fmaxf(pm, __shfl_xor_sync(0xffffffffu, pm, 4));
            pm = fmaxf(pm, __shfl_xor_sync(0xffffffffu, pm, 2));
            pm = fmaxf(pm, __shfl_xor_sync(0xffffffffu, pm, 1));
            float newm = fmaxf(mrow[i], pm);
            float fac  = __expf(mrow[i] - newm);
            float rs = 0.f;
#pragma unroll
            for (int jj = 0; jj < 4; jj++) {
                float p = __expf(s[i][jj] - newm);
                s[i][jj] = p;
                rs += p;
            }
            rs += __shfl_xor_sync(0xffffffffu, rs, 8);
            rs += __shfl_xor_sync(0xffffffffu, rs, 4);
            rs += __shfl_xor_sync(0xffffffffu, rs, 2);
            rs += __shfl_xor_sync(0xffffffffu, rs, 1);
            lrow[i] = lrow[i]*fac + rs;
            mrow[i] = newm;
#pragma unroll
            for (int c = 0; c < 8; c++) o[i][c] *= fac;
#pragma unroll
            for (int jj = 0; jj < 4; jj++)
                Ps[((tx<<2)+jj)*68 + (ty<<2)+i] = s[i][jj];
        }
        __syncthreads();
#pragma unroll
        for (int t2 = 0; t2 < 8; t2++) {
            int r  = (tid >> 3) + ((t2 & 1) << 5);
            int dq = (tid & 7) + ((t2 >> 1) << 3);
            float4 v = make_float4(0.f, 0.f, 0.f, 0.f);
            if (k0 + r < T) v = *(const float4*)(Vg + (size_t)(k0 + r)*BTL + (dq<<2));
            *(float4*)&KV[r*128 + (dq<<2)] = v;
        }
        __syncthreads();
#pragma unroll 2
        for (int kk = 0; kk < 64; kk++) {
            float4 pv = *(const float4*)&Ps[kk*68 + (ty<<2)];
            float4 v0 = *(const float4*)&KV[kk*128 + (tx<<3)];
            float4 v1 = *(const float4*)&KV[kk*128 + (tx<<3) + 4];
            float pa[4] = {pv.x, pv.y, pv.z, pv.w};
            float vv[8] = {v0.x, v0.y, v0.z, v0.w, v1.x, v1.y, v1.z, v1.w};
#pragma unroll
            for (int i = 0; i < 4; i++)
#pragma unroll
                for (int c = 0; c < 8; c++) o[i][c] += pa[i]*vv[c];
        }
    }
#pragma unroll
    for (int i = 0; i < 4; i++) {
        int r = q0 + (ty<<2) + i;
        if (r < T) {
            float inv = 1.f / lrow[i];
            float* dst = g_o + ((size_t)be*NN + r)*BTL + (tx<<3);
            *(float4*)dst     = make_float4(o[i][0]*inv, o[i][1]*inv, o[i][2]*inv, o[i][3]*inv);
            *(float4*)(dst+4) = make_float4(o[i][4]*inv, o[i][5]*inv, o[i][6]*inv, o[i][7]*inv);
        }
    }
}

// ---------------- up-proj + weighted combine ----------------
__global__ void __launch_bounds__(128) up_gemm(const float* __restrict__ Wu,
                                               float* __restrict__ out) {
    int be = blockIdx.y; int b = be >> 3, e = be & 7;
    int T  = g_cnt[be];
    int m0 = blockIdx.x << 6;
    if (m0 >= T) return;
    int col0 = blockIdx.z << 7;
    const float* Abase = g_o + (size_t)be*NN*BTL;
    const float* Bmat  = Wu + (size_t)e*BTL*DD;
    __shared__ float As[32*68];
    __shared__ float Bs[32*128];
    __shared__ int   rtok[64];
    __shared__ float rw[64];
    int tid = threadIdx.x;
    int ty = tid >> 4, tx = tid & 15;
    if (tid < 64) {
        int r = m0 + tid;
        rtok[tid] = (r < T) ? g_list[be*NN + r] : 0;
        rw[tid]   = (r < T) ? g_wlist[be*NN + r] : 0.f;
    }
    float acc[8][8];
#pragma unroll
    for (int i = 0; i < 8; i++)
#pragma unroll
        for (int j = 0; j < 8; j++) acc[i][j] = 0.f;
    for (int ko = 0; ko < BTL; ko += 32) {
        __syncthreads();
#pragma unroll
        for (int t2 = 0; t2 < 4; t2++) {
            int task = tid + (t2 << 7);
            int r = task >> 3, kq = task & 7;
            const float4 v = *(const float4*)(Abase + (size_t)(m0 + r)*BTL + ko + (kq<<2));
            As[(kq*4+0)*68 + r] = v.x;
            As[(kq*4+1)*68 + r] = v.y;
            As[(kq*4+2)*68 + r] = v.z;
            As[(kq*4+3)*68 + r] = v.w;
        }
#pragma unroll
        for (int t2 = 0; t2 < 8; t2++) {
            int task = tid + (t2 << 7);
            int kr = task >> 5, cq = task & 31;
            *(float4*)&Bs[kr*128 + (cq<<2)] =
                *(const float4*)(Bmat + (size_t)(ko + kr)*DD + col0 + (cq<<2));
        }
        __syncthreads();
        GEMM_MAIN(As, Bs, acc)
    }
#pragma unroll
    for (int i = 0; i < 8; i++) {
        int rl = (ty<<3) + i;
        if (m0 + rl < T) {
            int   tok = rtok[rl];
            float w   = rw[rl];
            float* dst = out + ((size_t)b*NN + tok)*DD + col0 + (tx<<3);
#pragma unroll
            for (int j = 0; j < 8; j++)
                atomicAdd(dst + j, w * acc[i][j]);
        }
    }
}

// ---------------- scalars ----------------
__global__ void finalize(float* out, int out_size) {
    if (threadIdx.x == 0 && blockIdx.x == 0) {
        float denom = fmaxf(g_act, 1.f);
        float lbl = 0.f, fmaxv = 0.f;
#pragma unroll
        for (int e = 0; e < EE; e++) {
            float fr = g_fsum[e] / denom;
            float pm = g_psum[e] / denom;
            lbl += fr * pm;
            fmaxv = fmaxf(fmaxv, fr);
        }
        lbl *= (float)EE / (float)TOPK;
        float vio = fmaxv / ((float)TOPK / (float)EE) - 1.f;
        if (out_size >= BND + 2) {
            out[BND]     = lbl;
            out[BND + 1] = vio;
        }
    }
}

extern "C" void kernel_launch(void* const* d_in, const int* in_sizes, int n_in,
                              void* d_out, int out_size) {
    const float* x   = (const float*)d_in[0];
    const int*   act = (const int*)d_in[2];
    const float* Wg = (const float*)d_in[3];
    const float* Wd = (const float*)d_in[4];
    const float* Wq = (const float*)d_in[5];
    const float* Wk = (const float*)d_in[6];
    const float* Wv = (const float*)d_in[7];
    const float* Wu = (const float*)d_in[8];
    float* out = (float*)d_out;

    cudaMemsetAsync(d_out, 0, (size_t)out_size * sizeof(float), 0);
    router_kernel<<<1024, 256>>>(x, Wg);
    router_reduce<<<1, 288>>>(act);
    build_lists<<<BE, 256>>>(act);
    dim3 g1(NN/64, BE, KSPLIT);
    down_gemm<<<g1, 128>>>(x, Wd);
    dim3 g2(NN/64, BE, 3);
    qkv_gemm<<<g2, 128>>>(Wq, Wk, Wv);
    cudaFuncSetAttribute(attn_kernel, cudaFuncAttributeMaxDynamicSharedMemorySize, ATTN_SMEM);
    dim3 g3(NN/64, BE);
    attn_kernel<<<g3, 256, ATTN_SMEM>>>();
    dim3 g4(NN/64, BE, DD/128);
    up_gemm<<<g4, 128>>>(Wu, out);
    finalize<<<1, 32>>>(out, out_size);
}